// round 7
// baseline (speedup 1.0000x reference)
#include <cuda_runtime.h>
#include <math_constants.h>

#define Nn 50000
#define Ee 800000
#define ET (Ee + Nn)        // edges + self loops
#define INC 128
#define HEADS 4
#define F1 256
#define OUTC 64
#define NEG 0.2f
#define NPB 64              // nodes per block gemm1
#define NPB2 32             // nodes per block gemm2
#define NCHUNK ((Nn + 255) / 256)   // 196

// ---------------- scratch ----------------
__device__ float4   g_h1[Nn * 64];      // layer1 features [n][64 f4]
__device__ float4   g_x2[Nn * 64];      // layer2 input (post ELU)
__device__ float4   g_h2[Nn * 16];      // layer2 features
__device__ float4   g_ss1[Nn];          // 4 head scores (src)
__device__ float4   g_sd1[Nn];
__device__ float    g_ss2[Nn];
__device__ float    g_sd2[Nn];
__device__ int      g_cnt[Nn];
__device__ int      g_offs[Nn + 1];
__device__ int      g_cursor[Nn];
__device__ int      g_bsum[NCHUNK];
__device__ int      g_src[ET];          // CSR: src ids grouped by dst
__device__ unsigned g_minbuf[OUTC];

__device__ __forceinline__ unsigned fenc(float f) {
    unsigned u = __float_as_uint(f);
    return (u & 0x80000000u) ? ~u : (u | 0x80000000u);
}
__device__ __forceinline__ float fdec(unsigned u) {
    return __uint_as_float((u & 0x80000000u) ? (u & 0x7FFFFFFFu) : ~u);
}
__device__ __forceinline__ float lrelu(float v) { return v > 0.f ? v : NEG * v; }
__device__ __forceinline__ float elu(float v) { return v > 0.f ? v : expm1f(v); }
__device__ __forceinline__ float dot4(float4 a, float4 b) {
    return a.x * b.x + a.y * b.y + a.z * b.z + a.w * b.w;
}

// ---------------- CSR build ----------------
__global__ void k_zero() {
    int i = blockIdx.x * blockDim.x + threadIdx.x;
    if (i < Nn) g_cnt[i] = 0;
    if (i < OUTC) g_minbuf[i] = 0xFFFFFFFFu;
}

__global__ void k_hist(const int* __restrict__ ei) {
    int e = blockIdx.x * blockDim.x + threadIdx.x;
    if (e >= ET) return;
    int d = (e < Ee) ? ei[Ee + e] : (e - Ee);
    atomicAdd(&g_cnt[d], 1);
}

__global__ void k_scanA() {
    __shared__ int sm[256];
    int t = threadIdx.x;
    int i = blockIdx.x * 256 + t;
    int v = (i < Nn) ? g_cnt[i] : 0;
    sm[t] = v;
    __syncthreads();
#pragma unroll
    for (int o = 1; o < 256; o <<= 1) {
        int y = (t >= o) ? sm[t - o] : 0;
        __syncthreads();
        sm[t] += y;
        __syncthreads();
    }
    if (i < Nn) g_offs[i] = sm[t] - v;
    if (t == 255) g_bsum[blockIdx.x] = sm[255];
}

// fused: every block scans the 196 chunk sums, applies its own offset
__global__ void k_scanBC() {
    __shared__ int sm[256];
    int t = threadIdx.x;
    sm[t] = (t < NCHUNK) ? g_bsum[t] : 0;
    __syncthreads();
#pragma unroll
    for (int o = 1; o < 256; o <<= 1) {
        int y = (t >= o) ? sm[t - o] : 0;
        __syncthreads();
        sm[t] += y;
        __syncthreads();
    }
    int ob = (blockIdx.x == 0) ? 0 : sm[blockIdx.x - 1];
    int i = blockIdx.x * 256 + t;
    if (i < Nn) {
        int o = g_offs[i] + ob;
        g_offs[i] = o;
        g_cursor[i] = o;
    }
    if (blockIdx.x == 0 && t == 0) g_offs[Nn] = ET;
}

__global__ void k_fill(const int* __restrict__ ei) {
    int e = blockIdx.x * blockDim.x + threadIdx.x;
    if (e >= ET) return;
    int s, d;
    if (e < Ee) { s = ei[e]; d = ei[Ee + e]; }
    else        { s = d = e - Ee; }
    int pos = atomicAdd(&g_cursor[d], 1);
    g_src[pos] = s;
}

// ---------------- layer 1 GEMM, split-N: 64 nodes x 128 feats per block -----
// grid (782, 2). blockIdx.y = feature half (heads 2fh, 2fh+1)
__global__ __launch_bounds__(512)
void k_gemm1(const float4* __restrict__ x4, const float4* __restrict__ W1_4,
             const float4* __restrict__ as4, const float4* __restrict__ ad4) {
    extern __shared__ float4 sm[];
    float4* sW = sm;                 // [128][32]  (k * 32 + fq)
    float4* sx = sm + INC * 32;      // [64][32]   (node * 32 + k4)

    int t = threadIdx.x;
    int n0 = blockIdx.x * NPB;
    int fh = blockIdx.y;             // 0 or 1
    int fbase = fh * 32;             // f4 offset into the 64-f4 row

    // load W half: rows k=0..127, f4 fbase..fbase+31
#pragma unroll
    for (int i = 0; i < 8; i++) {
        int idx = t + 512 * i;           // k = idx>>5, fq = idx&31
        sW[idx] = W1_4[(idx >> 5) * 64 + fbase + (idx & 31)];
    }
#pragma unroll
    for (int i = 0; i < 4; i++) {
        int idx = t + 512 * i;           // node = idx>>5, k4 = idx&31
        int n = n0 + (idx >> 5);
        sx[idx] = (n < Nn) ? x4[n * 32 + (idx & 31)] : make_float4(0.f, 0.f, 0.f, 0.f);
    }
    __syncthreads();

    int fq = t & 31;     // output f4 within half
    int mg = t >> 5;     // node group (4 nodes each), 0..15
    float4 acc[4];
#pragma unroll
    for (int m = 0; m < 4; m++) acc[m] = make_float4(0.f, 0.f, 0.f, 0.f);

    for (int k4 = 0; k4 < 32; k4++) {
        float4 w0 = sW[(k4 * 4 + 0) * 32 + fq];
        float4 w1 = sW[(k4 * 4 + 1) * 32 + fq];
        float4 w2 = sW[(k4 * 4 + 2) * 32 + fq];
        float4 w3 = sW[(k4 * 4 + 3) * 32 + fq];
#pragma unroll
        for (int m = 0; m < 4; m++) {
            float4 xv = sx[(mg * 4 + m) * 32 + k4];
            acc[m].x += xv.x * w0.x + xv.y * w1.x + xv.z * w2.x + xv.w * w3.x;
            acc[m].y += xv.x * w0.y + xv.y * w1.y + xv.z * w2.y + xv.w * w3.y;
            acc[m].z += xv.x * w0.z + xv.y * w1.z + xv.z * w2.z + xv.w * w3.z;
            acc[m].w += xv.x * w0.w + xv.y * w1.w + xv.z * w2.w + xv.w * w3.w;
        }
    }
#pragma unroll
    for (int m = 0; m < 4; m++) {
        int n = n0 + mg * 4 + m;
        if (n < Nn) g_h1[n * 64 + fbase + fq] = acc[m];
    }

    // fused scores: this block's 32 f4 = heads 2fh (fq 0-15) and 2fh+1 (fq 16-31)
    float4 av = as4[fbase + fq], dv = ad4[fbase + fq];
    float ps[4], pd[4];
#pragma unroll
    for (int m = 0; m < 4; m++) { ps[m] = dot4(acc[m], av); pd[m] = dot4(acc[m], dv); }
#pragma unroll
    for (int o = 8; o > 0; o >>= 1) {
#pragma unroll
        for (int m = 0; m < 4; m++) {
            ps[m] += __shfl_down_sync(0xFFFFFFFFu, ps[m], o, 16);
            pd[m] += __shfl_down_sync(0xFFFFFFFFu, pd[m], o, 16);
        }
    }
    if ((fq & 15) == 0) {
        int head = fh * 2 + (fq >> 4);
        float* gss = (float*)g_ss1;
        float* gsd = (float*)g_sd1;
#pragma unroll
        for (int m = 0; m < 4; m++) {
            int n = n0 + mg * 4 + m;
            if (n < Nn) { gss[n * 4 + head] = ps[m]; gsd[n * 4 + head] = pd[m]; }
        }
    }
}

// ---------------- layer 1 gather-aggregate: warp per dst, 4x unrolled -------
__global__ void k_agg1(const float4* __restrict__ b1_4) {
    int d = (blockIdx.x * blockDim.x + threadIdx.x) >> 5;
    int l = threadIdx.x & 31;
    if (d >= Nn) return;
    int off = g_offs[d];
    int deg = g_offs[d + 1] - off;
    int g2 = l >> 4;

    float4 dvv = g_sd1[d];
    float sda = g2 ? dvv.y : dvv.x;
    float sdb = g2 ? dvv.w : dvv.z;

    float4 acca = make_float4(0.f, 0.f, 0.f, 0.f);
    float4 accb = make_float4(0.f, 0.f, 0.f, 0.f);
    float dena = 0.f, denb = 0.f;

    for (int base = 0; base < deg; base += 32) {
        int sv = (base + l < deg) ? g_src[off + base + l] : 0;
        int m = deg - base; if (m > 32) m = 32;
        int jj = 0;
        for (; jj + 4 <= m; jj += 4) {
            int s0 = __shfl_sync(0xFFFFFFFFu, sv, jj);
            int s1 = __shfl_sync(0xFFFFFFFFu, sv, jj + 1);
            int s2 = __shfl_sync(0xFFFFFFFFu, sv, jj + 2);
            int s3 = __shfl_sync(0xFFFFFFFFu, sv, jj + 3);
            float4 c0 = g_ss1[s0], c1 = g_ss1[s1], c2 = g_ss1[s2], c3 = g_ss1[s3];
            float4 va0 = g_h1[s0 * 64 + l], vb0 = g_h1[s0 * 64 + 32 + l];
            float4 va1 = g_h1[s1 * 64 + l], vb1 = g_h1[s1 * 64 + 32 + l];
            float4 va2 = g_h1[s2 * 64 + l], vb2 = g_h1[s2 * 64 + 32 + l];
            float4 va3 = g_h1[s3 * 64 + l], vb3 = g_h1[s3 * 64 + 32 + l];
            float wa0 = __expf(lrelu((g2 ? c0.y : c0.x) + sda));
            float wb0 = __expf(lrelu((g2 ? c0.w : c0.z) + sdb));
            float wa1 = __expf(lrelu((g2 ? c1.y : c1.x) + sda));
            float wb1 = __expf(lrelu((g2 ? c1.w : c1.z) + sdb));
            float wa2 = __expf(lrelu((g2 ? c2.y : c2.x) + sda));
            float wb2 = __expf(lrelu((g2 ? c2.w : c2.z) + sdb));
            float wa3 = __expf(lrelu((g2 ? c3.y : c3.x) + sda));
            float wb3 = __expf(lrelu((g2 ? c3.w : c3.z) + sdb));
            acca.x += wa0 * va0.x + wa1 * va1.x + wa2 * va2.x + wa3 * va3.x;
            acca.y += wa0 * va0.y + wa1 * va1.y + wa2 * va2.y + wa3 * va3.y;
            acca.z += wa0 * va0.z + wa1 * va1.z + wa2 * va2.z + wa3 * va3.z;
            acca.w += wa0 * va0.w + wa1 * va1.w + wa2 * va2.w + wa3 * va3.w;
            accb.x += wb0 * vb0.x + wb1 * vb1.x + wb2 * vb2.x + wb3 * vb3.x;
            accb.y += wb0 * vb0.y + wb1 * vb1.y + wb2 * vb2.y + wb3 * vb3.y;
            accb.z += wb0 * vb0.z + wb1 * vb1.z + wb2 * vb2.z + wb3 * vb3.z;
            accb.w += wb0 * vb0.w + wb1 * vb1.w + wb2 * vb2.w + wb3 * vb3.w;
            dena += wa0 + wa1 + wa2 + wa3;
            denb += wb0 + wb1 + wb2 + wb3;
        }
        for (; jj < m; jj++) {
            int s = __shfl_sync(0xFFFFFFFFu, sv, jj);
            float4 sc = g_ss1[s];
            float wa = __expf(lrelu((g2 ? sc.y : sc.x) + sda));
            float wb = __expf(lrelu((g2 ? sc.w : sc.z) + sdb));
            float4 va = g_h1[s * 64 + l];
            float4 vb = g_h1[s * 64 + 32 + l];
            acca.x += wa * va.x; acca.y += wa * va.y; acca.z += wa * va.z; acca.w += wa * va.w;
            accb.x += wb * vb.x; accb.y += wb * vb.y; accb.z += wb * vb.z; accb.w += wb * vb.w;
            dena += wa; denb += wb;
        }
    }
    float ra = 1.f / dena, rb = 1.f / denb;
    float4 ba = b1_4[l], bb = b1_4[32 + l];
    float4 oa, ob;
    oa.x = elu(acca.x * ra + ba.x); oa.y = elu(acca.y * ra + ba.y);
    oa.z = elu(acca.z * ra + ba.z); oa.w = elu(acca.w * ra + ba.w);
    ob.x = elu(accb.x * rb + bb.x); ob.y = elu(accb.y * rb + bb.y);
    ob.z = elu(accb.z * rb + bb.z); ob.w = elu(accb.w * rb + bb.w);
    g_x2[d * 64 + l] = oa;
    g_x2[d * 64 + 32 + l] = ob;
}

// ---------------- layer 2 GEMM + fused scores (256 thr, 32 nodes) -----------
__global__ __launch_bounds__(256)
void k_gemm2(const float* __restrict__ W2,
             const float* __restrict__ as2, const float* __restrict__ ad2) {
    extern __shared__ float smf[];
    float* sWt = smf;                       // [64][260] padded
    float4* sWt4 = (float4*)sWt;
    float4* sx24 = (float4*)(smf + 64 * 260);
    __shared__ float s_ps[8][8], s_pd[8][8];

    int t = threadIdx.x;
    int n0 = blockIdx.x * NPB2;

    for (int idx = t; idx < F1 * OUTC; idx += 256) {
        int k = idx >> 6, f = idx & 63;
        sWt[f * 260 + k] = W2[idx];
    }
#pragma unroll
    for (int i = 0; i < 8; i++) {
        int idx = t + 256 * i;               // node = idx>>6, k4 = idx&63
        int n = n0 + (idx >> 6);
        sx24[idx] = (n < Nn) ? g_x2[n * 64 + (idx & 63)] : make_float4(0.f, 0.f, 0.f, 0.f);
    }
    __syncthreads();

    int f = t & 63;
    int mg = t >> 6;     // 0..3, 8 nodes each
    float acc[8];
#pragma unroll
    for (int m = 0; m < 8; m++) acc[m] = 0.f;

    for (int k4 = 0; k4 < 64; k4++) {
        float4 w4 = sWt4[f * 65 + k4];
#pragma unroll
        for (int m = 0; m < 8; m++) {
            float4 x4 = sx24[(mg * 8 + m) * 64 + k4];
            acc[m] += x4.x * w4.x + x4.y * w4.y + x4.z * w4.z + x4.w * w4.w;
        }
    }
#pragma unroll
    for (int m = 0; m < 8; m++) {
        int n = n0 + mg * 8 + m;
        if (n < Nn) ((float*)g_h2)[n * 64 + f] = acc[m];
    }

    // fused scores
    float av = as2[f], dv = ad2[f];
    float ps[8], pd[8];
#pragma unroll
    for (int m = 0; m < 8; m++) { ps[m] = acc[m] * av; pd[m] = acc[m] * dv; }
#pragma unroll
    for (int o = 16; o > 0; o >>= 1) {
#pragma unroll
        for (int m = 0; m < 8; m++) {
            ps[m] += __shfl_down_sync(0xFFFFFFFFu, ps[m], o);
            pd[m] += __shfl_down_sync(0xFFFFFFFFu, pd[m], o);
        }
    }
    int w = t >> 5;
    if ((t & 31) == 0) {
#pragma unroll
        for (int m = 0; m < 8; m++) { s_ps[w][m] = ps[m]; s_pd[w][m] = pd[m]; }
    }
    __syncthreads();
    if (t < 32) {
        int mg2 = t >> 3, m = t & 7;
        int n = n0 + mg2 * 8 + m;
        if (n < Nn) {
            g_ss2[n] = s_ps[2 * mg2][m] + s_ps[2 * mg2 + 1][m];
            g_sd2[n] = s_pd[2 * mg2][m] + s_pd[2 * mg2 + 1][m];
        }
    }
}

// ---------------- layer 2 gather-aggregate + fused column-min, 4x unrolled --
__global__ void k_agg2(const float* __restrict__ b2) {
    __shared__ float smin[8 * 64];
    int w = threadIdx.x >> 5;
    int l = threadIdx.x & 31;
    int d = (blockIdx.x << 3) + w;

    float v0 = CUDART_INF_F, v1 = CUDART_INF_F;
    if (d < Nn) {
        int off = g_offs[d];
        int deg = g_offs[d + 1] - off;
        float sdd = g_sd2[d];
        const float* h2f = (const float*)g_h2;
        float acc0 = 0.f, acc1 = 0.f, den = 0.f;
        for (int base = 0; base < deg; base += 32) {
            int sv = (base + l < deg) ? g_src[off + base + l] : 0;
            int m = deg - base; if (m > 32) m = 32;
            int jj = 0;
            for (; jj + 4 <= m; jj += 4) {
                int s0 = __shfl_sync(0xFFFFFFFFu, sv, jj);
                int s1 = __shfl_sync(0xFFFFFFFFu, sv, jj + 1);
                int s2 = __shfl_sync(0xFFFFFFFFu, sv, jj + 2);
                int s3 = __shfl_sync(0xFFFFFFFFu, sv, jj + 3);
                float e0 = g_ss2[s0], e1 = g_ss2[s1], e2 = g_ss2[s2], e3 = g_ss2[s3];
                float p00 = h2f[s0 * 64 + l], p01 = h2f[s0 * 64 + 32 + l];
                float p10 = h2f[s1 * 64 + l], p11 = h2f[s1 * 64 + 32 + l];
                float p20 = h2f[s2 * 64 + l], p21 = h2f[s2 * 64 + 32 + l];
                float p30 = h2f[s3 * 64 + l], p31 = h2f[s3 * 64 + 32 + l];
                float w0 = __expf(lrelu(e0 + sdd));
                float w1 = __expf(lrelu(e1 + sdd));
                float w2 = __expf(lrelu(e2 + sdd));
                float w3 = __expf(lrelu(e3 + sdd));
                acc0 += w0 * p00 + w1 * p10 + w2 * p20 + w3 * p30;
                acc1 += w0 * p01 + w1 * p11 + w2 * p21 + w3 * p31;
                den += w0 + w1 + w2 + w3;
            }
            for (; jj < m; jj++) {
                int s = __shfl_sync(0xFFFFFFFFu, sv, jj);
                float wgt = __expf(lrelu(g_ss2[s] + sdd));
                acc0 += wgt * h2f[s * 64 + l];
                acc1 += wgt * h2f[s * 64 + 32 + l];
                den += wgt;
            }
        }
        float r = 1.f / den;
        v0 = acc0 * r + b2[l];
        v1 = acc1 * r + b2[32 + l];
    }
    smin[w * 64 + l] = v0;
    smin[w * 64 + 32 + l] = v1;
    __syncthreads();
    if (threadIdx.x < 64) {
        int f = threadIdx.x;
        float m = smin[f];
#pragma unroll
        for (int i = 1; i < 8; i++) m = fminf(m, smin[i * 64 + f]);
        atomicMin(&g_minbuf[f], fenc(m));
    }
}

__global__ void k_write(float* __restrict__ out) {
    int t = threadIdx.x;
    if (t < OUTC) out[t] = fdec(g_minbuf[t]);
}

// ---------------- side stream + events ----------------
struct SideStream {
    cudaStream_t s;
    cudaEvent_t evF, evJ;
    SideStream() {
        cudaStreamCreateWithFlags(&s, cudaStreamNonBlocking);
        cudaEventCreateWithFlags(&evF, cudaEventDisableTiming);
        cudaEventCreateWithFlags(&evJ, cudaEventDisableTiming);
    }
};
static SideStream g_side;

// ---------------- launch ----------------
extern "C" void kernel_launch(void* const* d_in, const int* in_sizes, int n_in,
                              void* d_out, int out_size) {
    const float* x   = (const float*)d_in[0];
    const int*   ei  = (const int*)d_in[1];
    const float* W1  = (const float*)d_in[2];
    const float* as1 = (const float*)d_in[3];
    const float* ad1 = (const float*)d_in[4];
    const float* b1  = (const float*)d_in[5];
    const float* W2  = (const float*)d_in[6];
    const float* as2 = (const float*)d_in[7];
    const float* ad2 = (const float*)d_in[8];
    const float* b2  = (const float*)d_in[9];
    float* out = (float*)d_out;

    static int configured = 0;
    const int SMEM1 = (INC * 32 + NPB * 32) * 16;    // 98304
    const int SMEM2 = 64 * 260 * 4 + NPB2 * F1 * 4;  // 99328
    if (!configured) {
        cudaFuncSetAttribute(k_gemm1, cudaFuncAttributeMaxDynamicSharedMemorySize, SMEM1);
        cudaFuncSetAttribute(k_gemm2, cudaFuncAttributeMaxDynamicSharedMemorySize, SMEM2);
        configured = 1;
    }

    int eblk = (ET + 255) / 256;         // 3321

    // fork: CSR build on side stream, concurrent with gemm1
    cudaEventRecord(g_side.evF, 0);
    cudaStreamWaitEvent(g_side.s, g_side.evF, 0);
    k_zero<<<NCHUNK, 256, 0, g_side.s>>>();                  // 0
    k_hist<<<eblk, 256, 0, g_side.s>>>(ei);                  // 1
    k_scanA<<<NCHUNK, 256, 0, g_side.s>>>();                 // 2

    dim3 g1((Nn + NPB - 1) / NPB, 2);    // (782, 2)
    k_gemm1<<<g1, 512, SMEM1>>>((const float4*)x, (const float4*)W1,
                                (const float4*)as1, (const float4*)ad1);  // 3 (profiled)

    k_scanBC<<<NCHUNK, 256, 0, g_side.s>>>();                // 4
    k_fill<<<eblk, 256, 0, g_side.s>>>(ei);                  // 5
    cudaEventRecord(g_side.evJ, g_side.s);

    // join: agg1 needs both CSR and gemm1 results
    cudaStreamWaitEvent(0, g_side.evJ, 0);

    k_agg1<<<(Nn + 7) / 8, 256>>>((const float4*)b1);
    k_gemm2<<<(Nn + NPB2 - 1) / NPB2, 256, SMEM2>>>(W2, as2, ad2);
    k_agg2<<<(Nn + 7) / 8, 256>>>(b2);
    k_write<<<1, 64>>>(out);
}

// round 8
// speedup vs baseline: 1.0514x; 1.0514x over previous
#include <cuda_runtime.h>
#include <cuda_fp16.h>
#include <math_constants.h>

#define Nn 50000
#define Ee 800000
#define ET (Ee + Nn)        // edges + self loops
#define INC 128
#define HEADS 4
#define F1 256
#define OUTC 64
#define NEG 0.2f
#define NPB 64              // nodes per block gemm1
#define NPB2 32             // nodes per block gemm2
#define NCHUNK ((Nn + 255) / 256)   // 196

// ---------------- scratch ----------------
__device__ uint2    g_h1h[Nn * 64];     // layer1 features fp16 [n][256 halfs = 64 uint2]
__device__ float4   g_x2[Nn * 64];      // layer2 input (post ELU, fp32)
__device__ __half   g_h2h[Nn * 64];     // layer2 features fp16
__device__ float4   g_ss1[Nn];          // 4 head scores (src)
__device__ float4   g_sd1[Nn];
__device__ float    g_ss2[Nn];
__device__ float    g_sd2[Nn];
__device__ int      g_cnt[Nn];
__device__ int      g_offs[Nn + 1];
__device__ int      g_cursor[Nn];
__device__ int      g_bsum[NCHUNK];
__device__ int      g_src[ET];          // CSR: src ids grouped by dst
__device__ unsigned g_minbuf[OUTC];

__device__ __forceinline__ unsigned fenc(float f) {
    unsigned u = __float_as_uint(f);
    return (u & 0x80000000u) ? ~u : (u | 0x80000000u);
}
__device__ __forceinline__ float fdec(unsigned u) {
    return __uint_as_float((u & 0x80000000u) ? (u & 0x7FFFFFFFu) : ~u);
}
__device__ __forceinline__ float lrelu(float v) { return v > 0.f ? v : NEG * v; }
__device__ __forceinline__ float elu(float v) { return v > 0.f ? v : expm1f(v); }
__device__ __forceinline__ float dot4(float4 a, float4 b) {
    return a.x * b.x + a.y * b.y + a.z * b.z + a.w * b.w;
}
__device__ __forceinline__ uint2 f4_to_h4(float4 v) {
    __half2 a = __floats2half2_rn(v.x, v.y);
    __half2 b = __floats2half2_rn(v.z, v.w);
    uint2 r;
    r.x = *(unsigned*)&a;
    r.y = *(unsigned*)&b;
    return r;
}
__device__ __forceinline__ void acc8(float* acc, float w, uint4 r) {
    float2 f0 = __half22float2(*(__half2*)&r.x);
    float2 f1 = __half22float2(*(__half2*)&r.y);
    float2 f2 = __half22float2(*(__half2*)&r.z);
    float2 f3 = __half22float2(*(__half2*)&r.w);
    acc[0] += w * f0.x; acc[1] += w * f0.y;
    acc[2] += w * f1.x; acc[3] += w * f1.y;
    acc[4] += w * f2.x; acc[5] += w * f2.y;
    acc[6] += w * f3.x; acc[7] += w * f3.y;
}

// ---------------- CSR build ----------------
__global__ void k_zero() {
    int i = blockIdx.x * blockDim.x + threadIdx.x;
    if (i < Nn) g_cnt[i] = 0;
    if (i < OUTC) g_minbuf[i] = 0xFFFFFFFFu;
}

__global__ void k_hist(const int* __restrict__ ei) {
    int e = blockIdx.x * blockDim.x + threadIdx.x;
    if (e >= ET) return;
    int d = (e < Ee) ? ei[Ee + e] : (e - Ee);
    atomicAdd(&g_cnt[d], 1);
}

__global__ void k_scanA() {
    __shared__ int sm[256];
    int t = threadIdx.x;
    int i = blockIdx.x * 256 + t;
    int v = (i < Nn) ? g_cnt[i] : 0;
    sm[t] = v;
    __syncthreads();
#pragma unroll
    for (int o = 1; o < 256; o <<= 1) {
        int y = (t >= o) ? sm[t - o] : 0;
        __syncthreads();
        sm[t] += y;
        __syncthreads();
    }
    if (i < Nn) g_offs[i] = sm[t] - v;
    if (t == 255) g_bsum[blockIdx.x] = sm[255];
}

__global__ void k_scanBC() {
    __shared__ int sm[256];
    int t = threadIdx.x;
    sm[t] = (t < NCHUNK) ? g_bsum[t] : 0;
    __syncthreads();
#pragma unroll
    for (int o = 1; o < 256; o <<= 1) {
        int y = (t >= o) ? sm[t - o] : 0;
        __syncthreads();
        sm[t] += y;
        __syncthreads();
    }
    int ob = (blockIdx.x == 0) ? 0 : sm[blockIdx.x - 1];
    int i = blockIdx.x * 256 + t;
    if (i < Nn) {
        int o = g_offs[i] + ob;
        g_offs[i] = o;
        g_cursor[i] = o;
    }
    if (blockIdx.x == 0 && t == 0) g_offs[Nn] = ET;
}

__global__ void k_fill(const int* __restrict__ ei) {
    int e = blockIdx.x * blockDim.x + threadIdx.x;
    if (e >= ET) return;
    int s, d;
    if (e < Ee) { s = ei[e]; d = ei[Ee + e]; }
    else        { s = d = e - Ee; }
    int pos = atomicAdd(&g_cursor[d], 1);
    g_src[pos] = s;
}

// ---------------- layer 1 GEMM, split-N: 64 nodes x 128 feats per block -----
__global__ __launch_bounds__(512)
void k_gemm1(const float4* __restrict__ x4, const float4* __restrict__ W1_4,
             const float4* __restrict__ as4, const float4* __restrict__ ad4) {
    extern __shared__ float4 sm[];
    float4* sW = sm;                 // [128][32]
    float4* sx = sm + INC * 32;      // [64][32]

    int t = threadIdx.x;
    int n0 = blockIdx.x * NPB;
    int fh = blockIdx.y;
    int fbase = fh * 32;

#pragma unroll
    for (int i = 0; i < 8; i++) {
        int idx = t + 512 * i;
        sW[idx] = W1_4[(idx >> 5) * 64 + fbase + (idx & 31)];
    }
#pragma unroll
    for (int i = 0; i < 4; i++) {
        int idx = t + 512 * i;
        int n = n0 + (idx >> 5);
        sx[idx] = (n < Nn) ? x4[n * 32 + (idx & 31)] : make_float4(0.f, 0.f, 0.f, 0.f);
    }
    __syncthreads();

    int fq = t & 31;
    int mg = t >> 5;
    float4 acc[4];
#pragma unroll
    for (int m = 0; m < 4; m++) acc[m] = make_float4(0.f, 0.f, 0.f, 0.f);

    for (int k4 = 0; k4 < 32; k4++) {
        float4 w0 = sW[(k4 * 4 + 0) * 32 + fq];
        float4 w1 = sW[(k4 * 4 + 1) * 32 + fq];
        float4 w2 = sW[(k4 * 4 + 2) * 32 + fq];
        float4 w3 = sW[(k4 * 4 + 3) * 32 + fq];
#pragma unroll
        for (int m = 0; m < 4; m++) {
            float4 xv = sx[(mg * 4 + m) * 32 + k4];
            acc[m].x += xv.x * w0.x + xv.y * w1.x + xv.z * w2.x + xv.w * w3.x;
            acc[m].y += xv.x * w0.y + xv.y * w1.y + xv.z * w2.y + xv.w * w3.y;
            acc[m].z += xv.x * w0.z + xv.y * w1.z + xv.z * w2.z + xv.w * w3.z;
            acc[m].w += xv.x * w0.w + xv.y * w1.w + xv.z * w2.w + xv.w * w3.w;
        }
    }
#pragma unroll
    for (int m = 0; m < 4; m++) {
        int n = n0 + mg * 4 + m;
        if (n < Nn) g_h1h[n * 64 + fbase + fq] = f4_to_h4(acc[m]);
    }

    // fused scores
    float4 av = as4[fbase + fq], dv = ad4[fbase + fq];
    float ps[4], pd[4];
#pragma unroll
    for (int m = 0; m < 4; m++) { ps[m] = dot4(acc[m], av); pd[m] = dot4(acc[m], dv); }
#pragma unroll
    for (int o = 8; o > 0; o >>= 1) {
#pragma unroll
        for (int m = 0; m < 4; m++) {
            ps[m] += __shfl_down_sync(0xFFFFFFFFu, ps[m], o, 16);
            pd[m] += __shfl_down_sync(0xFFFFFFFFu, pd[m], o, 16);
        }
    }
    if ((fq & 15) == 0) {
        int head = fh * 2 + (fq >> 4);
        float* gss = (float*)g_ss1;
        float* gsd = (float*)g_sd1;
#pragma unroll
        for (int m = 0; m < 4; m++) {
            int n = n0 + mg * 4 + m;
            if (n < Nn) { gss[n * 4 + head] = ps[m]; gsd[n * 4 + head] = pd[m]; }
        }
    }
}

// ---------------- layer 1 gather-aggregate: warp per dst, fp16 gather -------
// lane l owns 8 contiguous features 8l..8l+7 = exactly one head (l>>3)
__global__ void k_agg1(const float4* __restrict__ b1_4) {
    int d = (blockIdx.x * blockDim.x + threadIdx.x) >> 5;
    int l = threadIdx.x & 31;
    if (d >= Nn) return;
    int off = g_offs[d];
    int deg = g_offs[d + 1] - off;
    int h = l >> 3;

    const float* gss = (const float*)g_ss1;
    float sd = ((const float*)g_sd1)[d * 4 + h];
    const uint4* h1r = (const uint4*)g_h1h;   // [Nn*32] uint4, row = n*32

    float acc[8];
#pragma unroll
    for (int i = 0; i < 8; i++) acc[i] = 0.f;
    float den = 0.f;

    for (int base = 0; base < deg; base += 32) {
        int sv = (base + l < deg) ? g_src[off + base + l] : 0;
        int m = deg - base; if (m > 32) m = 32;
        int jj = 0;
        for (; jj + 4 <= m; jj += 4) {
            int s0 = __shfl_sync(0xFFFFFFFFu, sv, jj);
            int s1 = __shfl_sync(0xFFFFFFFFu, sv, jj + 1);
            int s2 = __shfl_sync(0xFFFFFFFFu, sv, jj + 2);
            int s3 = __shfl_sync(0xFFFFFFFFu, sv, jj + 3);
            float e0 = gss[s0 * 4 + h], e1 = gss[s1 * 4 + h];
            float e2 = gss[s2 * 4 + h], e3 = gss[s3 * 4 + h];
            uint4 r0 = h1r[s0 * 32 + l];
            uint4 r1 = h1r[s1 * 32 + l];
            uint4 r2 = h1r[s2 * 32 + l];
            uint4 r3 = h1r[s3 * 32 + l];
            float w0 = __expf(lrelu(e0 + sd));
            float w1 = __expf(lrelu(e1 + sd));
            float w2 = __expf(lrelu(e2 + sd));
            float w3 = __expf(lrelu(e3 + sd));
            acc8(acc, w0, r0);
            acc8(acc, w1, r1);
            acc8(acc, w2, r2);
            acc8(acc, w3, r3);
            den += w0 + w1 + w2 + w3;
        }
        for (; jj < m; jj++) {
            int s = __shfl_sync(0xFFFFFFFFu, sv, jj);
            float e = gss[s * 4 + h];
            uint4 r = h1r[s * 32 + l];
            float w = __expf(lrelu(e + sd));
            acc8(acc, w, r);
            den += w;
        }
    }
    float rinv = 1.f / den;
    float4 bA = b1_4[2 * l], bB = b1_4[2 * l + 1];
    float4 oA, oB;
    oA.x = elu(acc[0] * rinv + bA.x); oA.y = elu(acc[1] * rinv + bA.y);
    oA.z = elu(acc[2] * rinv + bA.z); oA.w = elu(acc[3] * rinv + bA.w);
    oB.x = elu(acc[4] * rinv + bB.x); oB.y = elu(acc[5] * rinv + bB.y);
    oB.z = elu(acc[6] * rinv + bB.z); oB.w = elu(acc[7] * rinv + bB.w);
    g_x2[d * 64 + 2 * l] = oA;
    g_x2[d * 64 + 2 * l + 1] = oB;
}

// ---------------- layer 2 GEMM + fused scores (256 thr, 32 nodes) -----------
__global__ __launch_bounds__(256)
void k_gemm2(const float* __restrict__ W2,
             const float* __restrict__ as2, const float* __restrict__ ad2) {
    extern __shared__ float smf[];
    float* sWt = smf;                       // [64][260] padded
    float4* sWt4 = (float4*)sWt;
    float4* sx24 = (float4*)(smf + 64 * 260);
    __shared__ float s_ps[8][8], s_pd[8][8];

    int t = threadIdx.x;
    int n0 = blockIdx.x * NPB2;

    for (int idx = t; idx < F1 * OUTC; idx += 256) {
        int k = idx >> 6, f = idx & 63;
        sWt[f * 260 + k] = W2[idx];
    }
#pragma unroll
    for (int i = 0; i < 8; i++) {
        int idx = t + 256 * i;
        int n = n0 + (idx >> 6);
        sx24[idx] = (n < Nn) ? g_x2[n * 64 + (idx & 63)] : make_float4(0.f, 0.f, 0.f, 0.f);
    }
    __syncthreads();

    int f = t & 63;
    int mg = t >> 6;
    float acc[8];
#pragma unroll
    for (int m = 0; m < 8; m++) acc[m] = 0.f;

    for (int k4 = 0; k4 < 64; k4++) {
        float4 w4 = sWt4[f * 65 + k4];
#pragma unroll
        for (int m = 0; m < 8; m++) {
            float4 x4 = sx24[(mg * 8 + m) * 64 + k4];
            acc[m] += x4.x * w4.x + x4.y * w4.y + x4.z * w4.z + x4.w * w4.w;
        }
    }
#pragma unroll
    for (int m = 0; m < 8; m++) {
        int n = n0 + mg * 8 + m;
        if (n < Nn) g_h2h[n * 64 + f] = __float2half_rn(acc[m]);
    }

    // fused scores (fp32)
    float av = as2[f], dv = ad2[f];
    float ps[8], pd[8];
#pragma unroll
    for (int m = 0; m < 8; m++) { ps[m] = acc[m] * av; pd[m] = acc[m] * dv; }
#pragma unroll
    for (int o = 16; o > 0; o >>= 1) {
#pragma unroll
        for (int m = 0; m < 8; m++) {
            ps[m] += __shfl_down_sync(0xFFFFFFFFu, ps[m], o);
            pd[m] += __shfl_down_sync(0xFFFFFFFFu, pd[m], o);
        }
    }
    int w = t >> 5;
    if ((t & 31) == 0) {
#pragma unroll
        for (int m = 0; m < 8; m++) { s_ps[w][m] = ps[m]; s_pd[w][m] = pd[m]; }
    }
    __syncthreads();
    if (t < 32) {
        int mg2 = t >> 3, m = t & 7;
        int n = n0 + mg2 * 8 + m;
        if (n < Nn) {
            g_ss2[n] = s_ps[2 * mg2][m] + s_ps[2 * mg2 + 1][m];
            g_sd2[n] = s_pd[2 * mg2][m] + s_pd[2 * mg2 + 1][m];
        }
    }
}

// ---------------- layer 2 gather-aggregate + fused column-min, fp16 gather --
// lane l owns features 2l, 2l+1 (one half2 load per edge)
__global__ void k_agg2(const float* __restrict__ b2) {
    __shared__ float smin[8 * 64];
    int w = threadIdx.x >> 5;
    int l = threadIdx.x & 31;
    int d = (blockIdx.x << 3) + w;

    float v0 = CUDART_INF_F, v1 = CUDART_INF_F;
    if (d < Nn) {
        int off = g_offs[d];
        int deg = g_offs[d + 1] - off;
        float sdd = g_sd2[d];
        const unsigned* h2r = (const unsigned*)g_h2h;   // [Nn*32] half2
        float a0 = 0.f, a1 = 0.f, den = 0.f;
        for (int base = 0; base < deg; base += 32) {
            int sv = (base + l < deg) ? g_src[off + base + l] : 0;
            int m = deg - base; if (m > 32) m = 32;
            int jj = 0;
            for (; jj + 4 <= m; jj += 4) {
                int s0 = __shfl_sync(0xFFFFFFFFu, sv, jj);
                int s1 = __shfl_sync(0xFFFFFFFFu, sv, jj + 1);
                int s2 = __shfl_sync(0xFFFFFFFFu, sv, jj + 2);
                int s3 = __shfl_sync(0xFFFFFFFFu, sv, jj + 3);
                float e0 = g_ss2[s0], e1 = g_ss2[s1], e2 = g_ss2[s2], e3 = g_ss2[s3];
                unsigned p0 = h2r[s0 * 32 + l], p1 = h2r[s1 * 32 + l];
                unsigned p2 = h2r[s2 * 32 + l], p3 = h2r[s3 * 32 + l];
                float w0 = __expf(lrelu(e0 + sdd));
                float w1 = __expf(lrelu(e1 + sdd));
                float w2 = __expf(lrelu(e2 + sdd));
                float w3 = __expf(lrelu(e3 + sdd));
                float2 f0 = __half22float2(*(__half2*)&p0);
                float2 f1 = __half22float2(*(__half2*)&p1);
                float2 f2 = __half22float2(*(__half2*)&p2);
                float2 f3 = __half22float2(*(__half2*)&p3);
                a0 += w0 * f0.x + w1 * f1.x + w2 * f2.x + w3 * f3.x;
                a1 += w0 * f0.y + w1 * f1.y + w2 * f2.y + w3 * f3.y;
                den += w0 + w1 + w2 + w3;
            }
            for (; jj < m; jj++) {
                int s = __shfl_sync(0xFFFFFFFFu, sv, jj);
                float wgt = __expf(lrelu(g_ss2[s] + sdd));
                unsigned p = h2r[s * 32 + l];
                float2 f = __half22float2(*(__half2*)&p);
                a0 += wgt * f.x;
                a1 += wgt * f.y;
                den += wgt;
            }
        }
        float r = 1.f / den;
        v0 = a0 * r + b2[2 * l];
        v1 = a1 * r + b2[2 * l + 1];
    }
    smin[w * 64 + 2 * l] = v0;
    smin[w * 64 + 2 * l + 1] = v1;
    __syncthreads();
    if (threadIdx.x < 64) {
        int f = threadIdx.x;
        float m = smin[f];
#pragma unroll
        for (int i = 1; i < 8; i++) m = fminf(m, smin[i * 64 + f]);
        atomicMin(&g_minbuf[f], fenc(m));
    }
}

__global__ void k_write(float* __restrict__ out) {
    int t = threadIdx.x;
    if (t < OUTC) out[t] = fdec(g_minbuf[t]);
}

// ---------------- side stream + events ----------------
struct SideStream {
    cudaStream_t s;
    cudaEvent_t evF, evJ;
    SideStream() {
        cudaStreamCreateWithFlags(&s, cudaStreamNonBlocking);
        cudaEventCreateWithFlags(&evF, cudaEventDisableTiming);
        cudaEventCreateWithFlags(&evJ, cudaEventDisableTiming);
    }
};
static SideStream g_side;

// ---------------- launch ----------------
extern "C" void kernel_launch(void* const* d_in, const int* in_sizes, int n_in,
                              void* d_out, int out_size) {
    const float* x   = (const float*)d_in[0];
    const int*   ei  = (const int*)d_in[1];
    const float* W1  = (const float*)d_in[2];
    const float* as1 = (const float*)d_in[3];
    const float* ad1 = (const float*)d_in[4];
    const float* b1  = (const float*)d_in[5];
    const float* W2  = (const float*)d_in[6];
    const float* as2 = (const float*)d_in[7];
    const float* ad2 = (const float*)d_in[8];
    const float* b2  = (const float*)d_in[9];
    float* out = (float*)d_out;

    static int configured = 0;
    const int SMEM1 = (INC * 32 + NPB * 32) * 16;    // 98304
    const int SMEM2 = 64 * 260 * 4 + NPB2 * F1 * 4;  // 99328
    if (!configured) {
        cudaFuncSetAttribute(k_gemm1, cudaFuncAttributeMaxDynamicSharedMemorySize, SMEM1);
        cudaFuncSetAttribute(k_gemm2, cudaFuncAttributeMaxDynamicSharedMemorySize, SMEM2);
        configured = 1;
    }

    int eblk = (ET + 255) / 256;

    // fork: CSR build on side stream, concurrent with gemm1
    cudaEventRecord(g_side.evF, 0);
    cudaStreamWaitEvent(g_side.s, g_side.evF, 0);
    k_zero<<<NCHUNK, 256, 0, g_side.s>>>();                  // 0
    k_hist<<<eblk, 256, 0, g_side.s>>>(ei);                  // 1
    k_scanA<<<NCHUNK, 256, 0, g_side.s>>>();                 // 2

    dim3 g1((Nn + NPB - 1) / NPB, 2);
    k_gemm1<<<g1, 512, SMEM1>>>((const float4*)x, (const float4*)W1,
                                (const float4*)as1, (const float4*)ad1);  // 3 (profiled)

    k_scanBC<<<NCHUNK, 256, 0, g_side.s>>>();                // 4
    k_fill<<<eblk, 256, 0, g_side.s>>>(ei);                  // 5
    cudaEventRecord(g_side.evJ, g_side.s);

    cudaStreamWaitEvent(0, g_side.evJ, 0);

    k_agg1<<<(Nn + 7) / 8, 256>>>((const float4*)b1);
    k_gemm2<<<(Nn + NPB2 - 1) / NPB2, 256, SMEM2>>>(W2, as2, ad2);
    k_agg2<<<(Nn + 7) / 8, 256>>>(b2);
    k_write<<<1, 64>>>(out);
}